// round 5
// baseline (speedup 1.0000x reference)
#include <cuda_runtime.h>
#include <cuda_bf16.h>
#include <math.h>

// out[b,t,f,c] = sum_{s<=t} w^{t-s} x[b,s,f] + mem[b,f,c] * w^{t+1},
// w = exp(clip(a[f]) + i*b[c])  ==> complex IIR  y[t] = w*y[t-1] + x[t], y[-1]=mem.
// Parallel-in-T: 16 chunks of 32; chunk sums compose via E_i = w^32 E_{i-1} + S_i.
// One thread owns all C=4 channels of one f  -> ILP=4 independent chains.

#define B_DIM 8
#define T_DIM 512
#define F_DIM 1024
#define C_DIM 4
#define LIMIT_F 0.0766433975f                 // log(F32_MAX)/1024 - 0.01
#define N_OUT   (B_DIM * T_DIM * F_DIM * C_DIM)
#define L_CHUNK 32
#define N_CHUNK 16
#define FT      16                            // f-values per block

__global__ __launch_bounds__(256, 4)
void outer_laplace_scan4(const float* __restrict__ x,
                         const float* __restrict__ mem_r,
                         const float* __restrict__ mem_i,
                         const float* __restrict__ a,
                         const float* __restrict__ b,
                         float* __restrict__ out,
                         int mode, long long cap_f2)
{
    __shared__ float2 Ssm[N_CHUNK][FT][C_DIM];   // chunk-end sums (8 KB)

    const int tid   = threadIdx.x;
    const int f_idx = tid & (FT - 1);
    const int chunk = tid >> 4;                  // 0..15

    const int bb = blockIdx.x >> 6;              // batch
    const int f0 = (blockIdx.x & 63) * FT;
    const int f  = f0 + f_idx;

    // ---- coefficients: w[c] and w^32[c] ----
    const float ac  = fminf(fmaxf(a[f], -LIMIT_F), -1e-8f);
    const float er  = expf(ac);
    const float erL = expf(ac * (float)L_CHUNK);
    float wr[C_DIM], wi[C_DIM], wLr[C_DIM], wLi[C_DIM];
    #pragma unroll
    for (int c = 0; c < C_DIM; ++c) {
        float bc = b[c];
        float sn, cs;  sincosf(bc, &sn, &cs);
        wr[c] = er * cs;  wi[c] = er * sn;
        float snL, csL; sincosf(bc * (float)L_CHUNK, &snL, &csL);
        wLr[c] = erL * csL;  wLi[c] = erL * snL;
    }

    const float* xp0 = x + ((size_t)bb * T_DIM + chunk * L_CHUNK) * F_DIM + f;

    // ---- phase 1: chunk-local scan from zero (4 independent chains) ----
    float yr[C_DIM], yi[C_DIM];
    #pragma unroll
    for (int c = 0; c < C_DIM; ++c) { yr[c] = 0.f; yi[c] = 0.f; }
    {
        const float* xp = xp0;
        #pragma unroll 8
        for (int k = 0; k < L_CHUNK; ++k) {
            float xv = __ldg(xp);  xp += F_DIM;
            #pragma unroll
            for (int c = 0; c < C_DIM; ++c) {
                float nyr = fmaf(wr[c], yr[c], fmaf(-wi[c], yi[c], xv));
                float nyi = fmaf(wr[c], yi[c], wi[c] * yr[c]);
                yr[c] = nyr;  yi[c] = nyi;
            }
        }
    }
    #pragma unroll
    for (int c = 0; c < C_DIM; ++c)
        Ssm[chunk][f_idx][c] = make_float2(yr[c], yi[c]);
    __syncthreads();

    // ---- carry: Horner over previous chunk sums, seeded by memory ----
    const int midx = ((bb << 10) + f) << 2;      // (b*1024+f)*4
    float4 m4r = *(const float4*)(mem_r + midx);
    float4 m4i = *(const float4*)(mem_i + midx);
    float cr[C_DIM] = {m4r.x, m4r.y, m4r.z, m4r.w};
    float ci[C_DIM] = {m4i.x, m4i.y, m4i.z, m4i.w};
    for (int j = 0; j < chunk; ++j) {            // <=15 iters, warp-uniform +-1
        #pragma unroll
        for (int c = 0; c < C_DIM; ++c) {
            float2 S  = Ssm[j][f_idx][c];
            float ncr = fmaf(wLr[c], cr[c], fmaf(-wLi[c], ci[c], S.x));
            float nci = fmaf(wLr[c], ci[c], fmaf(wLi[c], cr[c], S.y));
            cr[c] = ncr;  ci[c] = nci;
        }
    }
    #pragma unroll
    for (int c = 0; c < C_DIM; ++c) { yr[c] = cr[c]; yi[c] = ci[c]; }

    // ---- phase 2: re-scan with correct init, vector stores ----
    long long base = ((long long)bb * T_DIM + chunk * L_CHUNK) * (F_DIM * C_DIM)
                   + ((long long)f << 2);        // in complex elements
    const float* xp = xp0;

    if (mode == 0) {                             // interleaved complex64
        float4* ow = (float4*)((float2*)out + base);   // 2 float4 per t
        const long long stride4 = (long long)F_DIM * C_DIM / 2;  // float4 units
        #pragma unroll 8
        for (int k = 0; k < L_CHUNK; ++k) {
            float xv = __ldg(xp);  xp += F_DIM;
            #pragma unroll
            for (int c = 0; c < C_DIM; ++c) {
                float nyr = fmaf(wr[c], yr[c], fmaf(-wi[c], yi[c], xv));
                float nyi = fmaf(wr[c], yi[c], wi[c] * yr[c]);
                yr[c] = nyr;  yi[c] = nyi;
            }
            ow[0] = make_float4(yr[0], yi[0], yr[1], yi[1]);
            ow[1] = make_float4(yr[2], yi[2], yr[3], yi[3]);
            ow += stride4;
        }
    } else if (mode == 1) {                      // real part only
        float4* ow = (float4*)(out + base);
        const long long stride4 = (long long)F_DIM * C_DIM / 4;
        #pragma unroll 8
        for (int k = 0; k < L_CHUNK; ++k) {
            float xv = __ldg(xp);  xp += F_DIM;
            #pragma unroll
            for (int c = 0; c < C_DIM; ++c) {
                float nyr = fmaf(wr[c], yr[c], fmaf(-wi[c], yi[c], xv));
                float nyi = fmaf(wr[c], yi[c], wi[c] * yr[c]);
                yr[c] = nyr;  yi[c] = nyi;
            }
            *ow = make_float4(yr[0], yr[1], yr[2], yr[3]);
            ow += stride4;
        }
    } else {                                     // guarded interleaved
        float2* ob = (float2*)out;
        long long idx = base;
        const int stride = F_DIM * C_DIM;
        #pragma unroll 4
        for (int k = 0; k < L_CHUNK; ++k) {
            float xv = __ldg(xp);  xp += F_DIM;
            #pragma unroll
            for (int c = 0; c < C_DIM; ++c) {
                float nyr = fmaf(wr[c], yr[c], fmaf(-wi[c], yi[c], xv));
                float nyi = fmaf(wr[c], yi[c], wi[c] * yr[c]);
                yr[c] = nyr;  yi[c] = nyi;
                if (idx + c < cap_f2) ob[idx + c] = make_float2(yr[c], yi[c]);
            }
            idx += stride;
        }
    }
}

extern "C" void kernel_launch(void* const* d_in, const int* in_sizes, int n_in,
                              void* d_out, int out_size)
{
    const float* x     = nullptr;
    const float* mem_r = nullptr;
    const float* mem_i = nullptr;
    const float* a     = nullptr;
    const float* b     = nullptr;

    for (int i = 0; i < n_in; ++i) {
        switch (in_sizes[i]) {
            case B_DIM * T_DIM * F_DIM:
                x = (const float*)d_in[i]; break;
            case B_DIM * F_DIM * C_DIM:
                if (!mem_r) mem_r = (const float*)d_in[i];
                else        mem_i = (const float*)d_in[i];
                break;
            case F_DIM:
                a = (const float*)d_in[i]; break;
            case C_DIM:
                b = (const float*)d_in[i]; break;
            default: break;
        }
    }
    if (!x || !mem_r || !mem_i || !a || !b) {
        x     = (const float*)d_in[0];
        mem_r = (const float*)d_in[1];
        mem_i = (const float*)d_in[2];
        a     = (const float*)d_in[3];
        b     = (const float*)d_in[4];
    }

    int mode;
    long long cap_f2;
    if (out_size >= 2 * N_OUT)      { mode = 0; cap_f2 = N_OUT; }
    else if (out_size == N_OUT)     { mode = 1; cap_f2 = N_OUT; }
    else                            { mode = 2; cap_f2 = (long long)out_size / 2; }

    // 512 blocks x 256 threads: block = (batch, 16 f-values), thread = (chunk, f).
    outer_laplace_scan4<<<B_DIM * (F_DIM / FT), 256>>>(x, mem_r, mem_i, a, b,
                                                       (float*)d_out, mode, cap_f2);
}

// round 6
// speedup vs baseline: 1.1235x; 1.1235x over previous
#include <cuda_runtime.h>
#include <cuda_bf16.h>
#include <math.h>

// out[b,t,f,c] = sum_{s<=t} w^{t-s} x[b,s,f] + mem[b,f,c] * w^{t+1},
// w = exp(clip(a[f]) + i*b[c])  ==> complex IIR  y[t] = w*y[t-1] + x[t], y[-1]=mem.
// 16 chunks of 32 composed via E_i = w^32 E_{i-1} + S_i (exact Horner carry).
// Channel pairs packed into f32x2 (FFMA2): 4 packed ops update 2 complex chains.

#define B_DIM 8
#define T_DIM 512
#define F_DIM 1024
#define C_DIM 4
#define LIMIT_F 0.0766433975f                 // log(F32_MAX)/1024 - 0.01
#define N_OUT   (B_DIM * T_DIM * F_DIM * C_DIM)
#define L_CHUNK 32
#define N_CHUNK 16
#define FT      16                            // f-values per block
#define NTHR    512

typedef unsigned long long u64;

__device__ __forceinline__ u64 pack2(float lo, float hi) {
    u64 r; asm("mov.b64 %0, {%1, %2};" : "=l"(r) : "f"(lo), "f"(hi)); return r;
}
__device__ __forceinline__ void unpack2(u64 v, float& lo, float& hi) {
    asm("mov.b64 {%0, %1}, %2;" : "=f"(lo), "=f"(hi) : "l"(v));
}
__device__ __forceinline__ u64 fma2(u64 a, u64 b, u64 c) {
    u64 d; asm("fma.rn.f32x2 %0, %1, %2, %3;" : "=l"(d) : "l"(a), "l"(b), "l"(c)); return d;
}
__device__ __forceinline__ u64 mul2(u64 a, u64 b) {
    u64 d; asm("mul.rn.f32x2 %0, %1, %2;" : "=l"(d) : "l"(a), "l"(b)); return d;
}

__global__ __launch_bounds__(NTHR, 2)
void outer_laplace_pk(const float* __restrict__ x,
                      const float* __restrict__ mem_r,
                      const float* __restrict__ mem_i,
                      const float* __restrict__ a,
                      const float* __restrict__ b,
                      float* __restrict__ out,
                      int mode, long long cap_f2)
{
    __shared__ float xs[T_DIM * FT];                 // 32 KB x slice
    __shared__ u64 SsmR[N_CHUNK][FT][2];             // 4 KB chunk sums (real, packed)
    __shared__ u64 SsmI[N_CHUNK][FT][2];             // 4 KB (imag, packed)

    const int tid   = threadIdx.x;
    const int cp    = tid & 1;                       // channel pair 0 -> c{0,1}, 1 -> c{2,3}
    const int f_idx = (tid >> 1) & (FT - 1);
    const int chunk = tid >> 5;                      // warp id = chunk

    const int bb = blockIdx.x >> 6;                  // batch
    const int f0 = (blockIdx.x & 63) * FT;
    const int f  = f0 + f_idx;
    const int c0 = cp << 1;

    // ---- stage x[b, :, f0:f0+16] into smem ----
    const float4* xg = (const float4*)(x + (size_t)bb * T_DIM * F_DIM + f0);
    #pragma unroll 4
    for (int i = tid; i < T_DIM * 4; i += NTHR) {    // 2048 float4
        int t = i >> 2, q = i & 3;
        *(float4*)&xs[t * FT + q * 4] = xg[(size_t)t * (F_DIM / 4) + q];
    }

    // ---- coefficients: w[c0],w[c1] packed; w^32 packed ----
    const float ac  = fminf(fmaxf(a[f], -LIMIT_F), -1e-8f);
    const float er  = expf(ac);
    const float erL = expf(ac * (float)L_CHUNK);
    float b0 = b[c0], b1 = b[c0 + 1];
    float s0, cz0, s1, cz1;
    sincosf(b0, &s0, &cz0);  sincosf(b1, &s1, &cz1);
    const u64 Wr  = pack2(er * cz0,  er * cz1);
    const u64 Wi  = pack2(er * s0,   er * s1);
    const u64 Wni = pack2(-er * s0, -er * s1);
    sincosf(b0 * (float)L_CHUNK, &s0, &cz0);
    sincosf(b1 * (float)L_CHUNK, &s1, &cz1);
    const u64 WLr  = pack2(erL * cz0,  erL * cz1);
    const u64 WLi  = pack2(erL * s0,   erL * s1);
    const u64 WLni = pack2(-erL * s0, -erL * s1);

    __syncthreads();

    // ---- phase 1: chunk-local scan from zero ----
    u64 ur = 0ull, ui = 0ull;
    const float* xp = &xs[(chunk * L_CHUNK) * FT + f_idx];
    #pragma unroll 8
    for (int k = 0; k < L_CHUNK; ++k) {
        float xv = xp[k * FT];
        u64 xx = pack2(xv, xv);
        u64 nur = fma2(Wr, ur, fma2(Wni, ui, xx));
        u64 nui = fma2(Wr, ui, mul2(Wi, ur));
        ur = nur;  ui = nui;
    }
    SsmR[chunk][f_idx][cp] = ur;
    SsmI[chunk][f_idx][cp] = ui;
    __syncthreads();

    // ---- carry: Horner over previous chunk sums, seeded by memory ----
    const int mbase = (((bb << 10) + f) << 2) + c0;
    u64 cr = pack2(mem_r[mbase], mem_r[mbase + 1]);
    u64 ci = pack2(mem_i[mbase], mem_i[mbase + 1]);
    for (int j = 0; j < chunk; ++j) {                // warp-uniform, <=15 iters
        u64 Sr = SsmR[j][f_idx][cp];
        u64 Si = SsmI[j][f_idx][cp];
        u64 ncr = fma2(WLr, cr, fma2(WLni, ci, Sr));
        u64 nci = fma2(WLr, ci, fma2(WLi, cr, Si));
        cr = ncr;  ci = nci;
    }
    ur = cr;  ui = ci;

    // ---- phase 2: re-scan with correct init, vector stores ----
    long long bidx = ((long long)bb * T_DIM + chunk * L_CHUNK) * (F_DIM * C_DIM)
                   + (f << 2) + c0;                  // complex-element index

    if (mode == 0) {                                 // interleaved complex64
        float4* ow = (float4*)((float2*)out + bidx);
        const long long stride4 = (long long)F_DIM * C_DIM / 2;   // float4 units
        #pragma unroll 8
        for (int k = 0; k < L_CHUNK; ++k) {
            float xv = xp[k * FT];
            u64 xx = pack2(xv, xv);
            u64 nur = fma2(Wr, ur, fma2(Wni, ui, xx));
            u64 nui = fma2(Wr, ui, mul2(Wi, ur));
            ur = nur;  ui = nui;
            float r0, r1, i0, i1;
            unpack2(ur, r0, r1);  unpack2(ui, i0, i1);
            *ow = make_float4(r0, i0, r1, i1);
            ow += stride4;
        }
    } else if (mode == 1) {                          // real part only (float32 out)
        float2* ow = (float2*)(out + bidx);
        const long long stride2 = (long long)F_DIM * C_DIM / 2;   // float2 units
        #pragma unroll 8
        for (int k = 0; k < L_CHUNK; ++k) {
            float xv = xp[k * FT];
            u64 xx = pack2(xv, xv);
            u64 nur = fma2(Wr, ur, fma2(Wni, ui, xx));
            u64 nui = fma2(Wr, ui, mul2(Wi, ur));
            ur = nur;  ui = nui;
            float r0, r1, i0, i1;
            unpack2(ur, r0, r1);  unpack2(ui, i0, i1);
            *ow = make_float2(r0, r1);
            ow += stride2;
        }
    } else {                                         // guarded interleaved
        float2* ob = (float2*)out;
        long long idx = bidx;
        const int stride = F_DIM * C_DIM;
        #pragma unroll 4
        for (int k = 0; k < L_CHUNK; ++k) {
            float xv = xp[k * FT];
            u64 xx = pack2(xv, xv);
            u64 nur = fma2(Wr, ur, fma2(Wni, ui, xx));
            u64 nui = fma2(Wr, ui, mul2(Wi, ur));
            ur = nur;  ui = nui;
            float r0, r1, i0, i1;
            unpack2(ur, r0, r1);  unpack2(ui, i0, i1);
            if (idx     < cap_f2) ob[idx]     = make_float2(r0, i0);
            if (idx + 1 < cap_f2) ob[idx + 1] = make_float2(r1, i1);
            idx += stride;
        }
    }
}

extern "C" void kernel_launch(void* const* d_in, const int* in_sizes, int n_in,
                              void* d_out, int out_size)
{
    const float* x     = nullptr;
    const float* mem_r = nullptr;
    const float* mem_i = nullptr;
    const float* a     = nullptr;
    const float* b     = nullptr;

    for (int i = 0; i < n_in; ++i) {
        switch (in_sizes[i]) {
            case B_DIM * T_DIM * F_DIM:
                x = (const float*)d_in[i]; break;
            case B_DIM * F_DIM * C_DIM:
                if (!mem_r) mem_r = (const float*)d_in[i];
                else        mem_i = (const float*)d_in[i];
                break;
            case F_DIM:
                a = (const float*)d_in[i]; break;
            case C_DIM:
                b = (const float*)d_in[i]; break;
            default: break;
        }
    }
    if (!x || !mem_r || !mem_i || !a || !b) {
        x     = (const float*)d_in[0];
        mem_r = (const float*)d_in[1];
        mem_i = (const float*)d_in[2];
        a     = (const float*)d_in[3];
        b     = (const float*)d_in[4];
    }

    int mode;
    long long cap_f2;
    if (out_size >= 2 * N_OUT)      { mode = 0; cap_f2 = N_OUT; }
    else if (out_size == N_OUT)     { mode = 1; cap_f2 = N_OUT; }
    else                            { mode = 2; cap_f2 = (long long)out_size / 2; }

    // 512 blocks x 512 threads: block = (batch, 16 f), thread = (chunk, f, cpair).
    outer_laplace_pk<<<B_DIM * (F_DIM / FT), NTHR>>>(x, mem_r, mem_i, a, b,
                                                     (float*)d_out, mode, cap_f2);
}